// round 14
// baseline (speedup 1.0000x reference)
#include <cuda_runtime.h>
#include <cuda_bf16.h>
#include <cstdint>
#include <cstddef>

// ----------------------------------------------------------------------------
// Transformer attention, B=4, S=2048, D=1024.  Split-bf16 GEMMs (logical
// K'=3K) with deduped [hi|lo] storage.
//   dist = x·(Wq^T·Wk)·x^T          (M'  = Wk^T·Wq  precomputed)
//   out  = attn·(x·(Wo·Wv)^T)       (Wvo = Wo·Wv    precomputed)
//   xv^T computed directly as Wvo @ x^T (mode-4 epilogue -> v2T, no vbuf)
// Mainloop v2 (mid-stage barrier between ks2/ks3), mma.sync.m16n8k16,
// 128x128x64 tile, 4 warps (64x64), 3-stage cp.async, frag double buffering,
// 2 CTAs/SM.
// ----------------------------------------------------------------------------

#define S_LEN   2048
#define DMODEL  1024
#define BATCH   4
#define MTOT    8192
#define K1      3072            // logical (3 * 1024)
#define K2      6144            // logical (3 * 2048)
#define MSPLIT  4               // split-K chunks for M' / Wvo gemms

// ---------------- scratch (physical [hi|lo] layouts, ld = 2*K/3) ------------
__device__ __nv_bfloat16 g_x2   [(size_t)MTOT * 2048];
__device__ __nv_bfloat16 g_WM2  [(size_t)2048 * 2048];   // rows 0-1023: Wvo; 1024-2047: M'
__device__ __nv_bfloat16 g_Wo2  [(size_t)1024 * 2048];   // Wo split (A of Wvo gemm)
__device__ __nv_bfloat16 g_WqT2 [(size_t)1024 * 2048];   // Wq^T split: [d][a-hi|a-lo]
__device__ __nv_bfloat16 g_WkT2 [(size_t)1024 * 2048];
__device__ __nv_bfloat16 g_WvT2 [(size_t)1024 * 2048];   // Wv^T split (B of Wvo gemm)
__device__ float         g_Mpart[(size_t)2 * MSPLIT * 1024 * 1024];  // [M' | Wvo] partials
__device__ __nv_bfloat16 g_xm2  [(size_t)MTOT * 2048];   // XM split
__device__ __nv_bfloat16 g_v2T  [(size_t)BATCH * DMODEL * 4096];  // xv^T split
__device__ __nv_bfloat16 g_attn2[(size_t)BATCH * S_LEN  * 4096];

// ---------------- PTX helpers ----------------
__device__ __forceinline__ void mma16816(float c[4], const uint32_t a[4], const uint32_t b[2]) {
    asm volatile(
        "mma.sync.aligned.m16n8k16.row.col.f32.bf16.bf16.f32 "
        "{%0,%1,%2,%3}, {%4,%5,%6,%7}, {%8,%9}, {%0,%1,%2,%3};\n"
        : "+f"(c[0]), "+f"(c[1]), "+f"(c[2]), "+f"(c[3])
        : "r"(a[0]), "r"(a[1]), "r"(a[2]), "r"(a[3]), "r"(b[0]), "r"(b[1]));
}
__device__ __forceinline__ void ldsm_x4(uint32_t r[4], uint32_t addr) {
    asm volatile("ldmatrix.sync.aligned.m8n8.x4.shared.b16 {%0,%1,%2,%3}, [%4];\n"
                 : "=r"(r[0]), "=r"(r[1]), "=r"(r[2]), "=r"(r[3]) : "r"(addr));
}
__device__ __forceinline__ void cp16(uint32_t s, const void* g) {
    asm volatile("cp.async.cg.shared.global [%0], [%1], 16;\n" :: "r"(s), "l"(g));
}
#define CP_COMMIT()     asm volatile("cp.async.commit_group;\n" ::: "memory")
#define CP_WAIT(n)      asm volatile("cp.async.wait_group %0;\n" :: "n"(n) : "memory")

__device__ __forceinline__ uint32_t pk2(__nv_bfloat16 a, __nv_bfloat16 b) {
    return (uint32_t)__bfloat16_as_ushort(a) | ((uint32_t)__bfloat16_as_ushort(b) << 16);
}

// ---------------- GEMM: C[M,N] = op(scale * A'[M,K] @ B'[N,K]^T) ------------
// Logical K = 3*Kthird.  Physical A,B are [hi|lo], ld = 2*Kthird.
// Stage column remap: A: o>=2*Kthird -> o-2*Kthird ; B: o>=Kthird -> o-Kthird.
// mode 0: fp32 out (ld N, *scale), batch via blockIdx.z
// mode 1: dedup split out: hi at c, lo at c+N; ld 2N
// mode 3: split-K partial fp32: blockIdx.z = K-chunk; C chunk via strideC
// mode 4: xv^T: rows = j (0..1023), cols g -> batch g>>11, t = g&2047;
//         write v2T[(b*1024+j)*4096 + t] hi, +2048 lo (packed u32 pairs)
#define BM 128
#define BN 128
#define BK 64
#define NSTG 3
#define SROW 144                          // 64 bf16 = 128B data + 16B pad
#define A_BYTES (BM * SROW)               // 18432
#define STAGE_BYTES ((BM + BN) * SROW)    // 36864
#define GEMM_SMEM (NSTG * STAGE_BYTES)    // 110592  (2 CTAs/SM)

__device__ __forceinline__ void load_frags(uint32_t st, uint32_t aOff, uint32_t bOff,
                                           int ks, uint32_t ra[4][4], uint32_t rb[4][4]) {
    #pragma unroll
    for (int mi = 0; mi < 4; mi++)
        ldsm_x4(ra[mi], st + aOff + mi * 16 * SROW + ks * 32);
    #pragma unroll
    for (int np = 0; np < 4; np++)
        ldsm_x4(rb[np], st + bOff + np * 16 * SROW + ks * 32);
}

__global__ __launch_bounds__(128, 2)
void gemm_bf16(const __nv_bfloat16* __restrict__ A,
               const __nv_bfloat16* __restrict__ B,
               void* __restrict__ Cout,
               int K, int N,
               long long strideA, long long strideB, long long strideC,
               float scale, int mode)
{
    extern __shared__ __align__(16) unsigned char smem[];
    const uint32_t sbase = (uint32_t)__cvta_generic_to_shared(smem);

    const int Kthird = K / 3;
    const int ldAB   = 2 * Kthird;

    const int b = blockIdx.z;
    A += (size_t)b * strideA;
    B += (size_t)b * strideB;

    int kbeg = 0;
    int KT   = K / BK;
    if (mode == 3) {                       // split-K: z indexes a K-chunk
        const int chunk = K / (int)gridDim.z;
        kbeg = b * chunk;
        KT   = chunk / BK;
    }

    const int bm = blockIdx.y * BM;
    const int bn = blockIdx.x * BN;
    const int tid = threadIdx.x;

    // producer mapping: 8 threads/row (128B), 16 rows/pass, 8 passes
    const int prow = tid >> 3;            // 0..15
    const int pch  = tid & 7;
    const __nv_bfloat16* Ag = A + (size_t)(bm + prow) * ldAB + pch * 8;
    const __nv_bfloat16* Bg = B + (size_t)(bn + prow) * ldAB + pch * 8;
    const uint32_t sA = sbase + prow * SROW + pch * 16;
    const uint32_t sB = sbase + A_BYTES + prow * SROW + pch * 16;

    auto issue = [&](int kt, int stg) {
        const uint32_t st = stg * STAGE_BYTES;
        const int o  = kbeg + kt * BK;
        const int oa = (o >= 2 * Kthird) ? o - 2 * Kthird : o;
        const int ob = (o >= Kthird)     ? o - Kthird     : o;
        #pragma unroll
        for (int p = 0; p < 8; p++) {
            cp16(sA + st + p * 16 * SROW, Ag + oa + (size_t)(p * 16) * ldAB);
            cp16(sB + st + p * 16 * SROW, Bg + ob + (size_t)(p * 16) * ldAB);
        }
    };

    const int warp = tid >> 5;
    const int lane = tid & 31;
    const int wm = (warp & 1) * 64;
    const int wn = (warp >> 1) * 64;

    float acc[4][8][4];
    #pragma unroll
    for (int i = 0; i < 4; i++)
        #pragma unroll
        for (int j = 0; j < 8; j++)
            #pragma unroll
            for (int k = 0; k < 4; k++) acc[i][j][k] = 0.0f;

    const uint32_t aOff = (wm + (lane & 15)) * SROW + (lane >> 4) * 16;
    const uint32_t bOff = A_BYTES + (wn + (lane & 7) + ((lane & 16) >> 1)) * SROW
                        + ((lane >> 3) & 1) * 16;

    // prologue: fill two stages, arm stage 0, preload its ks0 fragments
    issue(0, 0); CP_COMMIT();
    issue(1, 1); CP_COMMIT();
    CP_WAIT(1);                 // stage 0 arrived ({0,1} outstanding -> 0 done)
    __syncthreads();            // make stage 0 visible to all warps

    uint32_t ra[2][4][4], rb[2][4][4];
    load_frags(sbase, aOff, bOff, 0, ra[0], rb[0]);

    int sRd = 0, sWr = 2;
    for (int kt = 0; kt < KT; kt++) {
        const uint32_t st = sbase + sRd * STAGE_BYTES;

        // safe: all warps passed the previous barrier, so their reads of
        // stage sWr (read in iteration kt-1) are complete.
        if (kt + 2 < KT) issue(kt + 2, sWr);
        CP_COMMIT();                // unconditional: keeps wait_group counting safe

        #pragma unroll
        for (int ks = 0; ks < 3; ks++) {
            const int cur = ks & 1;
            load_frags(st, aOff, bOff, ks + 1, ra[cur ^ 1], rb[cur ^ 1]);
            #pragma unroll
            for (int mi = 0; mi < 4; mi++)
                #pragma unroll
                for (int ni = 0; ni < 8; ni++)
                    mma16816(acc[mi][ni], ra[cur][mi], &rb[cur][ni >> 1][(ni & 1) * 2]);
        }

        // stage boundary: arm stage kt+1, preload its ks0 frags, then run ks3.
        CP_WAIT(1);                 // outstanding {kt+1, kt+2} -> kt+1 arrived
        __syncthreads();            // visibility + read-completion for next issue
        const int nRd = (sRd + 1 == NSTG) ? 0 : sRd + 1;
        if (kt + 1 < KT)
            load_frags(sbase + nRd * STAGE_BYTES, aOff, bOff, 0, ra[0], rb[0]);

        #pragma unroll
        for (int mi = 0; mi < 4; mi++)
            #pragma unroll
            for (int ni = 0; ni < 8; ni++)
                mma16816(acc[mi][ni], ra[1][mi], &rb[1][ni >> 1][(ni & 1) * 2]);

        sRd = nRd;
        if (++sWr == NSTG) sWr = 0;
    }

    // ---------------- epilogue ----------------
    #pragma unroll
    for (int mi = 0; mi < 4; mi++) {
        const int r0 = bm + wm + mi * 16 + (lane >> 2);
        #pragma unroll
        for (int ni = 0; ni < 8; ni++) {
            const int cl = wn + ni * 8 + (lane & 3) * 2;
            float v00 = acc[mi][ni][0], v01 = acc[mi][ni][1];
            float v10 = acc[mi][ni][2], v11 = acc[mi][ni][3];
            if (mode == 0 || mode == 3) {         // fp32 out
                float* C = (float*)Cout + (size_t)b * strideC;
                float2* p0 = (float2*)(C + (size_t)r0 * N + bn + cl);
                float2* p1 = (float2*)(C + (size_t)(r0 + 8) * N + bn + cl);
                *p0 = make_float2(v00 * scale, v01 * scale);
                *p1 = make_float2(v10 * scale, v11 * scale);
            } else if (mode == 1) {               // dedup split out
                __nv_bfloat16* D = (__nv_bfloat16*)Cout + (size_t)b * strideC;
                #pragma unroll
                for (int rr = 0; rr < 2; rr++) {
                    float a0 = rr ? v10 : v00, a1 = rr ? v11 : v01;
                    __nv_bfloat16 h0 = __float2bfloat16(a0), h1 = __float2bfloat16(a1);
                    __nv_bfloat16 l0 = __float2bfloat16(a0 - __bfloat162float(h0));
                    __nv_bfloat16 l1 = __float2bfloat16(a1 - __bfloat162float(h1));
                    __nv_bfloat16* d = D + (size_t)(r0 + rr * 8) * (2 * N) + bn + cl;
                    *(uint32_t*)d       = pk2(h0, h1);
                    *(uint32_t*)(d + N) = pk2(l0, l1);
                }
            } else {                              // mode 4: xv^T -> v2T
                const int g  = bn + cl;
                const int bb = g >> 11;
                const int t  = g & 2047;          // even; t,t+1 same batch
                __nv_bfloat16* V = (__nv_bfloat16*)Cout;
                #pragma unroll
                for (int rr = 0; rr < 2; rr++) {
                    float a0 = rr ? v10 : v00, a1 = rr ? v11 : v01;
                    const int j = r0 + rr * 8;    // 0..1023
                    __nv_bfloat16 h0 = __float2bfloat16(a0), h1 = __float2bfloat16(a1);
                    __nv_bfloat16 l0 = __float2bfloat16(a0 - __bfloat162float(h0));
                    __nv_bfloat16 l1 = __float2bfloat16(a1 - __bfloat162float(h1));
                    __nv_bfloat16* d = V + ((size_t)bb * 1024 + j) * 4096 + t;
                    *(uint32_t*)d          = pk2(h0, h1);
                    *(uint32_t*)(d + 2048) = pk2(l0, l1);
                }
            }
        }
    }
}

// ---------------- conversions (dedup [hi|lo] layout) ----------------
__device__ __forceinline__ void split8_store(const float* s, __nv_bfloat16* d, int K) {
    float4 a = *(const float4*)s;
    float4 b = *(const float4*)(s + 4);
    __nv_bfloat16 h[8], l[8];
    float v[8] = {a.x, a.y, a.z, a.w, b.x, b.y, b.z, b.w};
    #pragma unroll
    for (int i = 0; i < 8; i++) {
        h[i] = __float2bfloat16(v[i]);
        l[i] = __float2bfloat16(v[i] - __bfloat162float(h[i]));
    }
    *(uint4*)d       = make_uint4(pk2(h[0], h[1]), pk2(h[2], h[3]), pk2(h[4], h[5]), pk2(h[6], h[7]));
    *(uint4*)(d + K) = make_uint4(pk2(l[0], l[1]), pk2(l[2], l[3]), pk2(l[4], l[5]), pk2(l[6], l[7]));
}

// one launch: x (8M floats) -> x2, Wo (1M) -> Wo2
__global__ void conv_all(const float* __restrict__ x, const float* __restrict__ Wo,
                         __nv_bfloat16* __restrict__ x2, __nv_bfloat16* __restrict__ Wo2)
{
    const size_t idx = ((size_t)blockIdx.x * blockDim.x + threadIdx.x) * 8;
    if (idx < (size_t)MTOT * DMODEL) {
        int row = (int)(idx >> 10), k = (int)(idx & 1023);
        split8_store(x + idx, x2 + (size_t)row * 2048 + k, 1024);
    } else {
        size_t off = idx - (size_t)MTOT * DMODEL;
        int row = (int)(off >> 10), k = (int)(off & 1023);
        split8_store(Wo + off, Wo2 + (size_t)row * 2048 + k, 1024);
    }
}

// transposed split of Wq / Wk / Wv:  WT2[d][a-hi | a-lo], ld 2048
__global__ void conv_wT(const float* __restrict__ Wq, const float* __restrict__ Wk,
                        const float* __restrict__ Wv,
                        __nv_bfloat16* __restrict__ WqT2, __nv_bfloat16* __restrict__ WkT2,
                        __nv_bfloat16* __restrict__ WvT2)
{
    __shared__ float tile[32][33];
    const float* src = (blockIdx.z == 0) ? Wq : (blockIdx.z == 1) ? Wk : Wv;
    __nv_bfloat16* dst = (blockIdx.z == 0) ? WqT2 : (blockIdx.z == 1) ? WkT2 : WvT2;
    const int a0 = blockIdx.x * 32;
    const int d0 = blockIdx.y * 32;
    const int tx = threadIdx.x, ty = threadIdx.y;   // 32 x 8

    #pragma unroll
    for (int i = 0; i < 32; i += 8)
        tile[ty + i][tx] = src[(size_t)(a0 + ty + i) * 1024 + d0 + tx];
    __syncthreads();

    #pragma unroll
    for (int i = 0; i < 32; i += 8) {
        int d = d0 + ty + i;
        int a = a0 + tx;
        float v = tile[tx][ty + i];
        __nv_bfloat16 hi = __float2bfloat16(v);
        __nv_bfloat16 lo = __float2bfloat16(v - __bfloat162float(hi));
        __nv_bfloat16* p = dst + (size_t)d * 2048 + a;
        p[0] = hi; p[1024] = lo;
    }
}

// reduce split-K partials of M' (slab 0) and Wvo (slab 1); write dedup split
// into WM2: Wvo -> rows 0-1023, M' -> rows 1024-2047.
__global__ void reduceM(const float* __restrict__ part, __nv_bfloat16* __restrict__ WM2)
{
    int i = blockIdx.x * blockDim.x + threadIdx.x;      // 524288 threads
    size_t idx = (size_t)i * 4;                         // 0 .. 2M
    const int m = (int)(idx >> 20);                     // 0 = M', 1 = Wvo
    const size_t off = idx & 0xFFFFFu;                  // within 1M
    const float* base = part + (size_t)m * MSPLIT * 1024 * 1024;
    float4 s = make_float4(0.f, 0.f, 0.f, 0.f);
    #pragma unroll
    for (int z = 0; z < MSPLIT; z++) {
        float4 p = *(const float4*)(base + (size_t)z * 1024 * 1024 + off);
        s.x += p.x; s.y += p.y; s.z += p.z; s.w += p.w;
    }
    int e = (int)(off >> 10), d = (int)(off & 1023);
    float v[4] = {s.x, s.y, s.z, s.w};
    __nv_bfloat16 h[4], l[4];
    #pragma unroll
    for (int j = 0; j < 4; j++) {
        h[j] = __float2bfloat16(v[j]);
        l[j] = __float2bfloat16(v[j] - __bfloat162float(h[j]));
    }
    const int dstrow = (m == 0) ? 1024 + e : e;
    __nv_bfloat16* dd = WM2 + (size_t)dstrow * 2048 + d;
    *(uint2*)dd          = make_uint2(pk2(h[0], h[1]), pk2(h[2], h[3]));
    *(uint2*)(dd + 1024) = make_uint2(pk2(l[0], l[1]), pk2(l[2], l[3]));
}

// softmax over rows; write attn2 dedup [hi|lo], ld 4096
__global__ void softmax_kernel(const float* __restrict__ dist,
                               __nv_bfloat16* __restrict__ attn2)
{
    const int row = blockIdx.x;
    const int tid = threadIdx.x;                  // 256
    const float4* d4 = (const float4*)(dist + (size_t)row * S_LEN) + tid * 2;
    float4 v0 = d4[0], v1 = d4[1];
    float v[8] = {v0.x, v0.y, v0.z, v0.w, v1.x, v1.y, v1.z, v1.w};

    float m = v[0];
    #pragma unroll
    for (int i = 1; i < 8; i++) m = fmaxf(m, v[i]);
    __shared__ float red[8];
    #pragma unroll
    for (int o = 16; o; o >>= 1) m = fmaxf(m, __shfl_xor_sync(0xffffffffu, m, o));
    if ((tid & 31) == 0) red[tid >> 5] = m;
    __syncthreads();
    m = red[0];
    #pragma unroll
    for (int i = 1; i < 8; i++) m = fmaxf(m, red[i]);
    __syncthreads();

    float s = 0.0f;
    #pragma unroll
    for (int i = 0; i < 8; i++) { v[i] = __expf(v[i] - m); s += v[i]; }
    #pragma unroll
    for (int o = 16; o; o >>= 1) s += __shfl_xor_sync(0xffffffffu, s, o);
    if ((tid & 31) == 0) red[tid >> 5] = s;
    __syncthreads();
    float tot = 0.0f;
    #pragma unroll
    for (int i = 0; i < 8; i++) tot += red[i];
    const float inv = 1.0f / tot;

    uint32_t H[4], L[4];
    #pragma unroll
    for (int i = 0; i < 4; i++) {
        float p0 = v[2 * i] * inv, p1 = v[2 * i + 1] * inv;
        __nv_bfloat16 h0 = __float2bfloat16(p0), h1 = __float2bfloat16(p1);
        __nv_bfloat16 l0 = __float2bfloat16(p0 - __bfloat162float(h0));
        __nv_bfloat16 l1 = __float2bfloat16(p1 - __bfloat162float(h1));
        H[i] = pk2(h0, h1); L[i] = pk2(l0, l1);
    }
    __nv_bfloat16* a2 = attn2 + (size_t)row * 4096 + tid * 8;
    *(uint4*)(a2)        = make_uint4(H[0], H[1], H[2], H[3]);
    *(uint4*)(a2 + 2048) = make_uint4(L[0], L[1], L[2], L[3]);
}

// ---------------- launch ----------------
extern "C" void kernel_launch(void* const* d_in, const int* in_sizes, int n_in,
                              void* d_out, int out_size)
{
    (void)in_sizes; (void)n_in; (void)out_size;
    const float* x  = (const float*)d_in[0];
    const float* Wq = (const float*)d_in[1];
    const float* Wk = (const float*)d_in[2];
    const float* Wv = (const float*)d_in[3];
    const float* Wo = (const float*)d_in[4];

    float* out    = (float*)d_out;                       // [4,2048,1024]
    float* weight = out + (size_t)MTOT * DMODEL;         // [4,2048,2048]

    void *p_x2, *p_WM2, *p_Wo2, *p_WqT2, *p_WkT2, *p_WvT2, *p_Mpart, *p_xm2,
         *p_v2T, *p_attn2;
    cudaGetSymbolAddress(&p_x2,    g_x2);
    cudaGetSymbolAddress(&p_WM2,   g_WM2);
    cudaGetSymbolAddress(&p_Wo2,   g_Wo2);
    cudaGetSymbolAddress(&p_WqT2,  g_WqT2);
    cudaGetSymbolAddress(&p_WkT2,  g_WkT2);
    cudaGetSymbolAddress(&p_WvT2,  g_WvT2);
    cudaGetSymbolAddress(&p_Mpart, g_Mpart);
    cudaGetSymbolAddress(&p_xm2,   g_xm2);
    cudaGetSymbolAddress(&p_v2T,   g_v2T);
    cudaGetSymbolAddress(&p_attn2, g_attn2);

    __nv_bfloat16* x2    = (__nv_bfloat16*)p_x2;
    __nv_bfloat16* WM2   = (__nv_bfloat16*)p_WM2;
    __nv_bfloat16* Wo2   = (__nv_bfloat16*)p_Wo2;
    __nv_bfloat16* WqT2  = (__nv_bfloat16*)p_WqT2;
    __nv_bfloat16* WkT2  = (__nv_bfloat16*)p_WkT2;
    __nv_bfloat16* WvT2  = (__nv_bfloat16*)p_WvT2;
    float*         Mpart = (float*)p_Mpart;
    __nv_bfloat16* xm2   = (__nv_bfloat16*)p_xm2;
    __nv_bfloat16* v2T   = (__nv_bfloat16*)p_v2T;
    __nv_bfloat16* attn2 = (__nv_bfloat16*)p_attn2;

    cudaFuncSetAttribute(gemm_bf16, cudaFuncAttributeMaxDynamicSharedMemorySize, GEMM_SMEM);

    const float dist_scale = 0.044194173824159223f;   // (1024/2)^-0.5

    // 1) conversions: x + Wo (straight split), Wq/Wk/Wv (transposed split)
    conv_all<<<4608, 256>>>(x, Wo, x2, Wo2);
    conv_wT<<<dim3(32, 32, 3), dim3(32, 8)>>>(Wq, Wk, Wv, WqT2, WkT2, WvT2);

    // 2) M' = Wk^T @ Wq  and  Wvo = Wo @ Wv  (split-K partials), then reduce
    gemm_bf16<<<dim3(8, 8, MSPLIT), 128, GEMM_SMEM>>>(
        WkT2, WqT2, Mpart, K1, 1024, 0, 0, (long long)1024 * 1024, 1.0f, 3);
    gemm_bf16<<<dim3(8, 8, MSPLIT), 128, GEMM_SMEM>>>(
        Wo2, WvT2, Mpart + (size_t)MSPLIT * 1024 * 1024,
        K1, 1024, 0, 0, (long long)1024 * 1024, 1.0f, 3);
    reduceM<<<2048, 256>>>(Mpart, WM2);

    // 3a) XM = x2 @ M'^T -> xm2 (dedup split)
    gemm_bf16<<<dim3(8, 64, 1), 128, GEMM_SMEM>>>(
        x2, WM2 + (size_t)1024 * 2048, xm2, K1, 1024, 0, 0, 0, 1.0f, 1);

    // 3b) xv^T = Wvo @ x^T -> v2T directly (mode 4)
    gemm_bf16<<<dim3(64, 8, 1), 128, GEMM_SMEM>>>(
        WM2, x2, v2T, K1, MTOT, 0, 0, 0, 1.0f, 4);

    // 4) weight = scale * XM @ x^T   [4][2048][2048]
    gemm_bf16<<<dim3(16, 16, BATCH), 128, GEMM_SMEM>>>(
        xm2, x2, weight, K1, S_LEN,
        (long long)S_LEN * 2048, (long long)S_LEN * 2048, (long long)S_LEN * S_LEN,
        dist_scale, 0);

    // 5) softmax rows -> attn2 (dedup split)
    softmax_kernel<<<MTOT, 256>>>(weight, attn2);

    // 6) out = attn @ xv   [2048 x 1024] per batch -> d_out directly
    gemm_bf16<<<dim3(8, 16, BATCH), 128, GEMM_SMEM>>>(
        attn2, v2T, out, K2, 1024,
        (long long)S_LEN * 4096, (long long)DMODEL * 4096, (long long)S_LEN * DMODEL,
        1.0f, 0);
}

// round 15
// speedup vs baseline: 1.0663x; 1.0663x over previous
#include <cuda_runtime.h>
#include <cuda_bf16.h>
#include <cstdint>
#include <cstddef>

// ----------------------------------------------------------------------------
// Transformer attention, B=4, S=2048, D=1024.  Split-bf16 GEMMs (logical
// K'=3K) with deduped [hi|lo] storage.
//   dist = x·(Wq^T·Wk)·x^T          (M'  = Wk^T·Wq  precomputed)
//   out  = attn·(x·(Wo·Wv)^T)       (Wvo = Wo·Wv    precomputed)
// R13 kernels unchanged.  Launch graph forked into two streams so the two
// small weight-space GEMMs run concurrently with the conversions, and
// conv_vT overlaps the weight GEMM.
// ----------------------------------------------------------------------------

#define S_LEN   2048
#define DMODEL  1024
#define BATCH   4
#define MTOT    8192
#define K1      3072            // logical (3 * 1024)
#define K2      6144            // logical (3 * 2048)
#define MSPLIT  4               // split-K chunks for M' / Wvo gemms

// ---------------- scratch (physical [hi|lo] layouts, ld = 2*K/3) ------------
__device__ __nv_bfloat16 g_x2   [(size_t)MTOT * 2048];
__device__ __nv_bfloat16 g_WM2  [(size_t)2048 * 2048];   // rows 0-1023: Wvo; 1024-2047: M'
__device__ __nv_bfloat16 g_Wo2  [(size_t)1024 * 2048];   // Wo split (A of Wvo gemm)
__device__ __nv_bfloat16 g_WqT2 [(size_t)1024 * 2048];   // Wq^T split: [d][a-hi|a-lo]
__device__ __nv_bfloat16 g_WkT2 [(size_t)1024 * 2048];
__device__ __nv_bfloat16 g_WvT2 [(size_t)1024 * 2048];   // Wv^T split (B of Wvo gemm)
__device__ float         g_Mpart[(size_t)2 * MSPLIT * 1024 * 1024];  // [M' | Wvo] partials
__device__ __nv_bfloat16 g_xm2  [(size_t)MTOT * 2048];   // XM split
__device__ float         g_vbuf [(size_t)MTOT * DMODEL]; // xv = x @ Wvo^T (fp32)
__device__ __nv_bfloat16 g_v2T  [(size_t)BATCH * DMODEL * 4096];  // xv transposed split
__device__ __nv_bfloat16 g_attn2[(size_t)BATCH * S_LEN  * 4096];

// ---------------- PTX helpers ----------------
__device__ __forceinline__ void mma16816(float c[4], const uint32_t a[4], const uint32_t b[2]) {
    asm volatile(
        "mma.sync.aligned.m16n8k16.row.col.f32.bf16.bf16.f32 "
        "{%0,%1,%2,%3}, {%4,%5,%6,%7}, {%8,%9}, {%0,%1,%2,%3};\n"
        : "+f"(c[0]), "+f"(c[1]), "+f"(c[2]), "+f"(c[3])
        : "r"(a[0]), "r"(a[1]), "r"(a[2]), "r"(a[3]), "r"(b[0]), "r"(b[1]));
}
__device__ __forceinline__ void ldsm_x4(uint32_t r[4], uint32_t addr) {
    asm volatile("ldmatrix.sync.aligned.m8n8.x4.shared.b16 {%0,%1,%2,%3}, [%4];\n"
                 : "=r"(r[0]), "=r"(r[1]), "=r"(r[2]), "=r"(r[3]) : "r"(addr));
}
__device__ __forceinline__ void cp16(uint32_t s, const void* g) {
    asm volatile("cp.async.cg.shared.global [%0], [%1], 16;\n" :: "r"(s), "l"(g));
}
#define CP_COMMIT()     asm volatile("cp.async.commit_group;\n" ::: "memory")
#define CP_WAIT(n)      asm volatile("cp.async.wait_group %0;\n" :: "n"(n) : "memory")

__device__ __forceinline__ uint32_t pk2(__nv_bfloat16 a, __nv_bfloat16 b) {
    return (uint32_t)__bfloat16_as_ushort(a) | ((uint32_t)__bfloat16_as_ushort(b) << 16);
}

// ---------------- GEMM: C[M,N] = op(scale * A'[M,K] @ B'[N,K]^T) ------------
// Logical K = 3*Kthird.  Physical A,B are [hi|lo], ld = 2*Kthird.
// Stage column remap: A: o>=2*Kthird -> o-2*Kthird ; B: o>=Kthird -> o-Kthird.
// mode 0: fp32 out (ld N, *scale), batch via blockIdx.z
// mode 2: merged VXM: cols [0,1024)->Cout fp32 (ld 1024); [1024,2048)->aux
//         dedup split (ld 2048)
// mode 3: split-K partial fp32: blockIdx.z = K-chunk; C chunk via strideC
#define BM 128
#define BN 128
#define BK 64
#define NSTG 3
#define SROW 144                          // 64 bf16 = 128B data + 16B pad
#define A_BYTES (BM * SROW)               // 18432
#define STAGE_BYTES ((BM + BN) * SROW)    // 36864
#define GEMM_SMEM (NSTG * STAGE_BYTES)    // 110592  (2 CTAs/SM)

__device__ __forceinline__ void load_frags(uint32_t st, uint32_t aOff, uint32_t bOff,
                                           int ks, uint32_t ra[4][4], uint32_t rb[4][4]) {
    #pragma unroll
    for (int mi = 0; mi < 4; mi++)
        ldsm_x4(ra[mi], st + aOff + mi * 16 * SROW + ks * 32);
    #pragma unroll
    for (int np = 0; np < 4; np++)
        ldsm_x4(rb[np], st + bOff + np * 16 * SROW + ks * 32);
}

__global__ __launch_bounds__(128, 2)
void gemm_bf16(const __nv_bfloat16* __restrict__ A,
               const __nv_bfloat16* __restrict__ B,
               void* __restrict__ Cout,
               __nv_bfloat16* __restrict__ aux,
               int K, int N,
               long long strideA, long long strideB, long long strideC,
               float scale, int mode)
{
    extern __shared__ __align__(16) unsigned char smem[];
    const uint32_t sbase = (uint32_t)__cvta_generic_to_shared(smem);

    const int Kthird = K / 3;
    const int ldAB   = 2 * Kthird;

    const int b = blockIdx.z;
    A += (size_t)b * strideA;
    B += (size_t)b * strideB;

    int kbeg = 0;
    int KT   = K / BK;
    if (mode == 3) {                       // split-K: z indexes a K-chunk
        const int chunk = K / (int)gridDim.z;
        kbeg = b * chunk;
        KT   = chunk / BK;
    }

    const int bm = blockIdx.y * BM;
    const int bn = blockIdx.x * BN;
    const int tid = threadIdx.x;

    // producer mapping: 8 threads/row (128B), 16 rows/pass, 8 passes
    const int prow = tid >> 3;            // 0..15
    const int pch  = tid & 7;
    const __nv_bfloat16* Ag = A + (size_t)(bm + prow) * ldAB + pch * 8;
    const __nv_bfloat16* Bg = B + (size_t)(bn + prow) * ldAB + pch * 8;
    const uint32_t sA = sbase + prow * SROW + pch * 16;
    const uint32_t sB = sbase + A_BYTES + prow * SROW + pch * 16;

    auto issue = [&](int kt, int stg) {
        const uint32_t st = stg * STAGE_BYTES;
        const int o  = kbeg + kt * BK;
        const int oa = (o >= 2 * Kthird) ? o - 2 * Kthird : o;
        const int ob = (o >= Kthird)     ? o - Kthird     : o;
        #pragma unroll
        for (int p = 0; p < 8; p++) {
            cp16(sA + st + p * 16 * SROW, Ag + oa + (size_t)(p * 16) * ldAB);
            cp16(sB + st + p * 16 * SROW, Bg + ob + (size_t)(p * 16) * ldAB);
        }
    };

    const int warp = tid >> 5;
    const int lane = tid & 31;
    const int wm = (warp & 1) * 64;
    const int wn = (warp >> 1) * 64;

    float acc[4][8][4];
    #pragma unroll
    for (int i = 0; i < 4; i++)
        #pragma unroll
        for (int j = 0; j < 8; j++)
            #pragma unroll
            for (int k = 0; k < 4; k++) acc[i][j][k] = 0.0f;

    const uint32_t aOff = (wm + (lane & 15)) * SROW + (lane >> 4) * 16;
    const uint32_t bOff = A_BYTES + (wn + (lane & 7) + ((lane & 16) >> 1)) * SROW
                        + ((lane >> 3) & 1) * 16;

    // prologue: fill two stages, arm stage 0, preload its ks0 fragments
    issue(0, 0); CP_COMMIT();
    issue(1, 1); CP_COMMIT();
    CP_WAIT(1);                 // stage 0 arrived ({0,1} outstanding -> 0 done)
    __syncthreads();            // make stage 0 visible to all warps

    uint32_t ra[2][4][4], rb[2][4][4];
    load_frags(sbase, aOff, bOff, 0, ra[0], rb[0]);

    int sRd = 0, sWr = 2;
    for (int kt = 0; kt < KT; kt++) {
        const uint32_t st = sbase + sRd * STAGE_BYTES;

        // safe: all warps passed the previous barrier, so their reads of
        // stage sWr (read in iteration kt-1) are complete.
        if (kt + 2 < KT) issue(kt + 2, sWr);
        CP_COMMIT();                // unconditional: keeps wait_group counting safe

        #pragma unroll
        for (int ks = 0; ks < 3; ks++) {
            const int cur = ks & 1;
            load_frags(st, aOff, bOff, ks + 1, ra[cur ^ 1], rb[cur ^ 1]);
            #pragma unroll
            for (int mi = 0; mi < 4; mi++)
                #pragma unroll
                for (int ni = 0; ni < 8; ni++)
                    mma16816(acc[mi][ni], ra[cur][mi], &rb[cur][ni >> 1][(ni & 1) * 2]);
        }

        // stage boundary: arm stage kt+1, preload its ks0 frags, then run ks3.
        CP_WAIT(1);                 // outstanding {kt+1, kt+2} -> kt+1 arrived
        __syncthreads();            // visibility + read-completion for next issue
        const int nRd = (sRd + 1 == NSTG) ? 0 : sRd + 1;
        if (kt + 1 < KT)
            load_frags(sbase + nRd * STAGE_BYTES, aOff, bOff, 0, ra[0], rb[0]);

        #pragma unroll
        for (int mi = 0; mi < 4; mi++)
            #pragma unroll
            for (int ni = 0; ni < 8; ni++)
                mma16816(acc[mi][ni], ra[1][mi], &rb[1][ni >> 1][(ni & 1) * 2]);

        sRd = nRd;
        if (++sWr == NSTG) sWr = 0;
    }

    // ---------------- epilogue ----------------
    #pragma unroll
    for (int mi = 0; mi < 4; mi++) {
        const int r0 = bm + wm + mi * 16 + (lane >> 2);
        #pragma unroll
        for (int ni = 0; ni < 8; ni++) {
            const int cl = wn + ni * 8 + (lane & 3) * 2;
            float v00 = acc[mi][ni][0], v01 = acc[mi][ni][1];
            float v10 = acc[mi][ni][2], v11 = acc[mi][ni][3];
            if (mode != 2) {                      // fp32 out (modes 0 and 3)
                float* C = (float*)Cout + (size_t)b * strideC;
                float2* p0 = (float2*)(C + (size_t)r0 * N + bn + cl);
                float2* p1 = (float2*)(C + (size_t)(r0 + 8) * N + bn + cl);
                *p0 = make_float2(v00 * scale, v01 * scale);
                *p1 = make_float2(v10 * scale, v11 * scale);
            } else {                              // mode 2: merged VXM
                const int g = bn + cl;
                #pragma unroll
                for (int rr = 0; rr < 2; rr++) {
                    float a0 = rr ? v10 : v00, a1 = rr ? v11 : v01;
                    const size_t row = (size_t)(r0 + rr * 8);
                    if (g < 1024) {               // xv = x@Wvo^T -> fp32 vbuf
                        *(float2*)((float*)Cout + row * 1024 + g) = make_float2(a0, a1);
                    } else {                      // XM -> dedup split
                        const int c = g - 1024;
                        __nv_bfloat16 h0 = __float2bfloat16(a0), h1 = __float2bfloat16(a1);
                        __nv_bfloat16 l0 = __float2bfloat16(a0 - __bfloat162float(h0));
                        __nv_bfloat16 l1 = __float2bfloat16(a1 - __bfloat162float(h1));
                        __nv_bfloat16* d = aux + row * 2048 + c;
                        *(uint32_t*)d          = pk2(h0, h1);
                        *(uint32_t*)(d + 1024) = pk2(l0, l1);
                    }
                }
            }
        }
    }
}

// ---------------- conversions (dedup [hi|lo] layout) ----------------
__device__ __forceinline__ void split8_store(const float* s, __nv_bfloat16* d, int K) {
    float4 a = *(const float4*)s;
    float4 b = *(const float4*)(s + 4);
    __nv_bfloat16 h[8], l[8];
    float v[8] = {a.x, a.y, a.z, a.w, b.x, b.y, b.z, b.w};
    #pragma unroll
    for (int i = 0; i < 8; i++) {
        h[i] = __float2bfloat16(v[i]);
        l[i] = __float2bfloat16(v[i] - __bfloat162float(h[i]));
    }
    *(uint4*)d       = make_uint4(pk2(h[0], h[1]), pk2(h[2], h[3]), pk2(h[4], h[5]), pk2(h[6], h[7]));
    *(uint4*)(d + K) = make_uint4(pk2(l[0], l[1]), pk2(l[2], l[3]), pk2(l[4], l[5]), pk2(l[6], l[7]));
}

// one launch: x (8M floats) -> x2, Wo (1M) -> Wo2
__global__ void conv_all(const float* __restrict__ x, const float* __restrict__ Wo,
                         __nv_bfloat16* __restrict__ x2, __nv_bfloat16* __restrict__ Wo2)
{
    const size_t idx = ((size_t)blockIdx.x * blockDim.x + threadIdx.x) * 8;
    if (idx < (size_t)MTOT * DMODEL) {
        int row = (int)(idx >> 10), k = (int)(idx & 1023);
        split8_store(x + idx, x2 + (size_t)row * 2048 + k, 1024);
    } else {
        size_t off = idx - (size_t)MTOT * DMODEL;
        int row = (int)(off >> 10), k = (int)(off & 1023);
        split8_store(Wo + off, Wo2 + (size_t)row * 2048 + k, 1024);
    }
}

// transposed split of Wq / Wk / Wv:  WT2[d][a-hi | a-lo], ld 2048
__global__ void conv_wT(const float* __restrict__ Wq, const float* __restrict__ Wk,
                        const float* __restrict__ Wv,
                        __nv_bfloat16* __restrict__ WqT2, __nv_bfloat16* __restrict__ WkT2,
                        __nv_bfloat16* __restrict__ WvT2)
{
    __shared__ float tile[32][33];
    const float* src = (blockIdx.z == 0) ? Wq : (blockIdx.z == 1) ? Wk : Wv;
    __nv_bfloat16* dst = (blockIdx.z == 0) ? WqT2 : (blockIdx.z == 1) ? WkT2 : WvT2;
    const int a0 = blockIdx.x * 32;
    const int d0 = blockIdx.y * 32;
    const int tx = threadIdx.x, ty = threadIdx.y;   // 32 x 8

    #pragma unroll
    for (int i = 0; i < 32; i += 8)
        tile[ty + i][tx] = src[(size_t)(a0 + ty + i) * 1024 + d0 + tx];
    __syncthreads();

    #pragma unroll
    for (int i = 0; i < 32; i += 8) {
        int d = d0 + ty + i;
        int a = a0 + tx;
        float v = tile[tx][ty + i];
        __nv_bfloat16 hi = __float2bfloat16(v);
        __nv_bfloat16 lo = __float2bfloat16(v - __bfloat162float(hi));
        __nv_bfloat16* p = dst + (size_t)d * 2048 + a;
        p[0] = hi; p[1024] = lo;
    }
}

// reduce split-K partials of M' (slab 0) and Wvo (slab 1); write dedup split
// into WM2: Wvo -> rows 0-1023, M' -> rows 1024-2047.
__global__ void reduceM(const float* __restrict__ part, __nv_bfloat16* __restrict__ WM2)
{
    int i = blockIdx.x * blockDim.x + threadIdx.x;      // 524288 threads
    size_t idx = (size_t)i * 4;                         // 0 .. 2M
    const int m = (int)(idx >> 20);                     // 0 = M', 1 = Wvo
    const size_t off = idx & 0xFFFFFu;                  // within 1M
    const float* base = part + (size_t)m * MSPLIT * 1024 * 1024;
    float4 s = make_float4(0.f, 0.f, 0.f, 0.f);
    #pragma unroll
    for (int z = 0; z < MSPLIT; z++) {
        float4 p = *(const float4*)(base + (size_t)z * 1024 * 1024 + off);
        s.x += p.x; s.y += p.y; s.z += p.z; s.w += p.w;
    }
    int e = (int)(off >> 10), d = (int)(off & 1023);
    float v[4] = {s.x, s.y, s.z, s.w};
    __nv_bfloat16 h[4], l[4];
    #pragma unroll
    for (int j = 0; j < 4; j++) {
        h[j] = __float2bfloat16(v[j]);
        l[j] = __float2bfloat16(v[j] - __bfloat162float(h[j]));
    }
    const int dstrow = (m == 0) ? 1024 + e : e;
    __nv_bfloat16* dd = WM2 + (size_t)dstrow * 2048 + d;
    *(uint2*)dd          = make_uint2(pk2(h[0], h[1]), pk2(h[2], h[3]));
    *(uint2*)(dd + 1024) = make_uint2(pk2(l[0], l[1]), pk2(l[2], l[3]));
}

// xv transpose + split:  v2T[b][e] = [hi(t) | lo(t)+2048], ld 4096.
// 64 t x 32 j per block; each thread packs two adjacent t into one u32 store.
__global__ void conv_vT_kernel(const float* __restrict__ vbuf,
                               __nv_bfloat16* __restrict__ v2T)
{
    __shared__ float tile[64][33];
    const int b  = blockIdx.z;
    const int t0 = blockIdx.x * 64;
    const int j0 = blockIdx.y * 32;
    const int tx = threadIdx.x, ty = threadIdx.y;   // 32 x 8

    #pragma unroll
    for (int i = 0; i < 64; i += 8)
        tile[ty + i][tx] = vbuf[((size_t)(b * S_LEN + t0 + ty + i)) * DMODEL + j0 + tx];
    __syncthreads();

    #pragma unroll
    for (int i = 0; i < 32; i += 8) {
        const int j = j0 + ty + i;
        const int t = t0 + 2 * tx;
        float a0 = tile[2 * tx][ty + i];
        float a1 = tile[2 * tx + 1][ty + i];
        __nv_bfloat16 h0 = __float2bfloat16(a0), h1 = __float2bfloat16(a1);
        __nv_bfloat16 l0 = __float2bfloat16(a0 - __bfloat162float(h0));
        __nv_bfloat16 l1 = __float2bfloat16(a1 - __bfloat162float(h1));
        __nv_bfloat16* d = v2T + ((size_t)b * DMODEL + j) * 4096 + t;
        *(uint32_t*)d          = pk2(h0, h1);
        *(uint32_t*)(d + 2048) = pk2(l0, l1);
    }
}

// softmax over rows; write attn2 dedup [hi|lo], ld 4096
__global__ void softmax_kernel(const float* __restrict__ dist,
                               __nv_bfloat16* __restrict__ attn2)
{
    const int row = blockIdx.x;
    const int tid = threadIdx.x;                  // 256
    const float4* d4 = (const float4*)(dist + (size_t)row * S_LEN) + tid * 2;
    float4 v0 = d4[0], v1 = d4[1];
    float v[8] = {v0.x, v0.y, v0.z, v0.w, v1.x, v1.y, v1.z, v1.w};

    float m = v[0];
    #pragma unroll
    for (int i = 1; i < 8; i++) m = fmaxf(m, v[i]);
    __shared__ float red[8];
    #pragma unroll
    for (int o = 16; o; o >>= 1) m = fmaxf(m, __shfl_xor_sync(0xffffffffu, m, o));
    if ((tid & 31) == 0) red[tid >> 5] = m;
    __syncthreads();
    m = red[0];
    #pragma unroll
    for (int i = 1; i < 8; i++) m = fmaxf(m, red[i]);
    __syncthreads();

    float s = 0.0f;
    #pragma unroll
    for (int i = 0; i < 8; i++) { v[i] = __expf(v[i] - m); s += v[i]; }
    #pragma unroll
    for (int o = 16; o; o >>= 1) s += __shfl_xor_sync(0xffffffffu, s, o);
    if ((tid & 31) == 0) red[tid >> 5] = s;
    __syncthreads();
    float tot = 0.0f;
    #pragma unroll
    for (int i = 0; i < 8; i++) tot += red[i];
    const float inv = 1.0f / tot;

    uint32_t H[4], L[4];
    #pragma unroll
    for (int i = 0; i < 4; i++) {
        float p0 = v[2 * i] * inv, p1 = v[2 * i + 1] * inv;
        __nv_bfloat16 h0 = __float2bfloat16(p0), h1 = __float2bfloat16(p1);
        __nv_bfloat16 l0 = __float2bfloat16(p0 - __bfloat162float(h0));
        __nv_bfloat16 l1 = __float2bfloat16(p1 - __bfloat162float(h1));
        H[i] = pk2(h0, h1); L[i] = pk2(l0, l1);
    }
    __nv_bfloat16* a2 = attn2 + (size_t)row * 4096 + tid * 8;
    *(uint4*)(a2)        = make_uint4(H[0], H[1], H[2], H[3]);
    *(uint4*)(a2 + 2048) = make_uint4(L[0], L[1], L[2], L[3]);
}

// ---------------- launch ----------------
extern "C" void kernel_launch(void* const* d_in, const int* in_sizes, int n_in,
                              void* d_out, int out_size)
{
    (void)in_sizes; (void)n_in; (void)out_size;
    const float* x  = (const float*)d_in[0];
    const float* Wq = (const float*)d_in[1];
    const float* Wk = (const float*)d_in[2];
    const float* Wv = (const float*)d_in[3];
    const float* Wo = (const float*)d_in[4];

    float* out    = (float*)d_out;                       // [4,2048,1024]
    float* weight = out + (size_t)MTOT * DMODEL;         // [4,2048,2048]

    void *p_x2, *p_WM2, *p_Wo2, *p_WqT2, *p_WkT2, *p_WvT2, *p_Mpart, *p_xm2,
         *p_vbuf, *p_v2T, *p_attn2;
    cudaGetSymbolAddress(&p_x2,    g_x2);
    cudaGetSymbolAddress(&p_WM2,   g_WM2);
    cudaGetSymbolAddress(&p_Wo2,   g_Wo2);
    cudaGetSymbolAddress(&p_WqT2,  g_WqT2);
    cudaGetSymbolAddress(&p_WkT2,  g_WkT2);
    cudaGetSymbolAddress(&p_WvT2,  g_WvT2);
    cudaGetSymbolAddress(&p_Mpart, g_Mpart);
    cudaGetSymbolAddress(&p_xm2,   g_xm2);
    cudaGetSymbolAddress(&p_vbuf,  g_vbuf);
    cudaGetSymbolAddress(&p_v2T,   g_v2T);
    cudaGetSymbolAddress(&p_attn2, g_attn2);

    __nv_bfloat16* x2    = (__nv_bfloat16*)p_x2;
    __nv_bfloat16* WM2   = (__nv_bfloat16*)p_WM2;
    __nv_bfloat16* Wo2   = (__nv_bfloat16*)p_Wo2;
    __nv_bfloat16* WqT2  = (__nv_bfloat16*)p_WqT2;
    __nv_bfloat16* WkT2  = (__nv_bfloat16*)p_WkT2;
    __nv_bfloat16* WvT2  = (__nv_bfloat16*)p_WvT2;
    float*         Mpart = (float*)p_Mpart;
    __nv_bfloat16* xm2   = (__nv_bfloat16*)p_xm2;
    float*         vbuf  = (float*)p_vbuf;
    __nv_bfloat16* v2T   = (__nv_bfloat16*)p_v2T;
    __nv_bfloat16* attn2 = (__nv_bfloat16*)p_attn2;

    cudaFuncSetAttribute(gemm_bf16, cudaFuncAttributeMaxDynamicSharedMemorySize, GEMM_SMEM);

    // side stream + fork/join events (lazy handles; identical captured work
    // on every call)
    static cudaStream_t s2 = nullptr;
    static cudaEvent_t evFork = nullptr, evW = nullptr, evS1 = nullptr,
                       evX = nullptr, evV = nullptr;
    if (s2 == nullptr) {
        cudaStreamCreateWithFlags(&s2, cudaStreamNonBlocking);
        cudaEventCreateWithFlags(&evFork, cudaEventDisableTiming);
        cudaEventCreateWithFlags(&evW,    cudaEventDisableTiming);
        cudaEventCreateWithFlags(&evS1,   cudaEventDisableTiming);
        cudaEventCreateWithFlags(&evX,    cudaEventDisableTiming);
        cudaEventCreateWithFlags(&evV,    cudaEventDisableTiming);
    }

    const float dist_scale = 0.044194173824159223f;   // (1024/2)^-0.5

    // fork: branch 2 handles conv_wT -> M' gemm; main handles conv_all -> Wvo
    cudaEventRecord(evFork, 0);
    cudaStreamWaitEvent(s2, evFork, 0);

    // branch 2 (s2): transposed weight conversions, then M' split-K gemm
    conv_wT<<<dim3(32, 32, 3), dim3(32, 8), 0, s2>>>(Wq, Wk, Wv, WqT2, WkT2, WvT2);
    cudaEventRecord(evW, s2);
    gemm_bf16<<<dim3(8, 8, MSPLIT), 128, GEMM_SMEM, s2>>>(
        WkT2, WqT2, Mpart, nullptr, K1, 1024, 0, 0, (long long)1024 * 1024, 1.0f, 3);
    cudaEventRecord(evS1, s2);

    // main (stream 0): x + Wo conversion, then Wvo split-K gemm (needs WvT2)
    conv_all<<<4608, 256>>>(x, Wo, x2, Wo2);
    cudaStreamWaitEvent(0, evW, 0);
    gemm_bf16<<<dim3(8, 8, MSPLIT), 128, GEMM_SMEM>>>(
        Wo2, WvT2, Mpart + (size_t)MSPLIT * 1024 * 1024, nullptr,
        K1, 1024, 0, 0, (long long)1024 * 1024, 1.0f, 3);

    // join: reduce needs both partial sets
    cudaStreamWaitEvent(0, evS1, 0);
    reduceM<<<2048, 256>>>(Mpart, WM2);

    // merged VXM: x2 @ [Wvo ; M']^T -> vbuf=xv (fp32) + xm2 (split)
    gemm_bf16<<<dim3(16, 64, 1), 128, GEMM_SMEM>>>(
        x2, WM2, vbuf, xm2, K1, 2048, 0, 0, 0, 1.0f, 2);
    cudaEventRecord(evX, 0);

    // branch 2: conv_vT overlaps the weight gemm
    cudaStreamWaitEvent(s2, evX, 0);
    conv_vT_kernel<<<dim3(S_LEN / 64, DMODEL / 32, BATCH), dim3(32, 8), 0, s2>>>(vbuf, v2T);
    cudaEventRecord(evV, s2);

    // main: weight = scale * XM @ x^T, then softmax
    gemm_bf16<<<dim3(16, 16, BATCH), 128, GEMM_SMEM>>>(
        xm2, x2, weight, nullptr, K1, S_LEN,
        (long long)S_LEN * 2048, (long long)S_LEN * 2048, (long long)S_LEN * S_LEN,
        dist_scale, 0);
    softmax_kernel<<<MTOT, 256>>>(weight, attn2);

    // join: attn@xv needs v2T
    cudaStreamWaitEvent(0, evV, 0);
    gemm_bf16<<<dim3(8, 16, BATCH), 128, GEMM_SMEM>>>(
        attn2, v2T, out, nullptr, K2, 1024,
        (long long)S_LEN * 4096, (long long)DMODEL * 4096, (long long)S_LEN * DMODEL,
        1.0f, 0);
}